// round 8
// baseline (speedup 1.0000x reference)
#include <cuda_runtime.h>
#include <cuda_bf16.h>
#include <cstddef>

// ---------------------------------------------------------------------------
// Mamba-1 LM forward, fp32 SIMT baseline.
// B=4, L=2048, D=384, E=768, N=16, dt_rank=24, vocab=5000, 4 layers.
// Pipeline per layer:
//   rmsnorm -> in_proj GEMM -> conv+silu -> x_proj GEMM -> dt_proj(softplus)
//   -> selective scan (warp = 2 channels x 16 states) -> gate -> out_proj GEMM (+residual)
// then final rmsnorm + tied lm_head GEMM into d_out.
// ---------------------------------------------------------------------------

#define BATCHN 4
#define SEQ    2048
#define DMODEL 384
#define NLAYER 4
#define VOCABN 5000
#define DINNER 768
#define DSTATE 16
#define DTRANK 24
#define PROJC  (DTRANK + 2*DSTATE)   // 56
#define MTOT   (BATCHN*SEQ)          // 8192
#define TWOE   (2*DINNER)            // 1536

// -------------------- scratch (static device globals, no allocs) -----------
__device__ float g_x  [MTOT*DMODEL];
__device__ float g_xn [MTOT*DMODEL];
__device__ float g_xz [MTOT*TWOE];
__device__ float g_xin[MTOT*DINNER];
__device__ float g_proj[MTOT*PROJC];
__device__ float g_dt [MTOT*DINNER];
__device__ float g_ys [MTOT*DINNER];
__device__ float g_y  [MTOT*DINNER];

// -------------------- embedding gather -------------------------------------
__global__ void embed_gather_kernel(const int* __restrict__ tok,
                                    const float* __restrict__ emb,
                                    float* __restrict__ x) {
    int idx = blockIdx.x * blockDim.x + threadIdx.x;
    if (idx >= MTOT * DMODEL) return;
    int m = idx / DMODEL;
    int d = idx - m * DMODEL;
    x[idx] = emb[(size_t)tok[m] * DMODEL + d];
}

// -------------------- rmsnorm (warp per row of 384) -------------------------
__global__ void rmsnorm_kernel(const float* __restrict__ x,
                               const float* __restrict__ w,
                               float* __restrict__ o) {
    int row  = blockIdx.x * blockDim.y + threadIdx.y;
    int lane = threadIdx.x;
    const float* xr = x + (size_t)row * DMODEL;
    float v[12];
    float ss = 0.f;
#pragma unroll
    for (int i = 0; i < 12; i++) { v[i] = xr[lane + i*32]; ss = fmaf(v[i], v[i], ss); }
#pragma unroll
    for (int off = 16; off > 0; off >>= 1)
        ss += __shfl_xor_sync(0xffffffffu, ss, off);
    float sc = rsqrtf(ss * (1.0f/DMODEL) + 1e-5f);
    float* orow = o + (size_t)row * DMODEL;
#pragma unroll
    for (int i = 0; i < 12; i++)
        orow[lane + i*32] = v[i] * sc * w[lane + i*32];
}

// -------------------- SGEMM: C[M,N] = A[M,K] * W[N,K]^T (+residual) ---------
template<int BM, int BN, int BK, int TM, int TN, bool RESID>
__global__ __launch_bounds__((BM/TM)*(BN/TN))
void sgemm_kernel(const float* __restrict__ A, const float* __restrict__ W,
                  float* __restrict__ C, const float* __restrict__ R,
                  int M, int N, int K) {
    constexpr int KG = BK / 4;
    __shared__ float As[BK][BM + 4];
    __shared__ float Bs[BK][BN + 4];

    const int t  = threadIdx.x;
    const int m0 = blockIdx.y * BM;
    const int n0 = blockIdx.x * BN;

    const int lrow = t / KG;
    const int lk   = (t % KG) * 4;

    const float* Ap = A + (size_t)(m0 + lrow) * K + lk;
    const int   wrow = n0 + lrow;
    const bool  wv   = wrow < N;
    const float* Wp  = W + (size_t)wrow * K + lk;

    float4 ra = *(const float4*)Ap;
    float4 rb = wv ? *(const float4*)Wp : make_float4(0.f,0.f,0.f,0.f);

    const int trow = t / (BN/TN);
    const int tcol = t % (BN/TN);

    float acc[TM][TN];
#pragma unroll
    for (int i = 0; i < TM; i++)
#pragma unroll
        for (int j = 0; j < TN; j++) acc[i][j] = 0.f;

    const int nK = K / BK;
    for (int kt = 0; kt < nK; kt++) {
        As[lk+0][lrow] = ra.x; As[lk+1][lrow] = ra.y;
        As[lk+2][lrow] = ra.z; As[lk+3][lrow] = ra.w;
        Bs[lk+0][lrow] = rb.x; Bs[lk+1][lrow] = rb.y;
        Bs[lk+2][lrow] = rb.z; Bs[lk+3][lrow] = rb.w;
        __syncthreads();

        if (kt + 1 < nK) {
            Ap += BK; Wp += BK;
            ra = *(const float4*)Ap;
            rb = wv ? *(const float4*)Wp : make_float4(0.f,0.f,0.f,0.f);
        }

#pragma unroll
        for (int kk = 0; kk < BK; kk++) {
            float a[TM], b[TN];
#pragma unroll
            for (int h = 0; h < TM/4; h++) {
                float4 v = *(const float4*)&As[kk][h*(BM/2) + trow*4];
                a[h*4+0]=v.x; a[h*4+1]=v.y; a[h*4+2]=v.z; a[h*4+3]=v.w;
            }
#pragma unroll
            for (int h = 0; h < TN/4; h++) {
                float4 v = *(const float4*)&Bs[kk][h*(BN/2) + tcol*4];
                b[h*4+0]=v.x; b[h*4+1]=v.y; b[h*4+2]=v.z; b[h*4+3]=v.w;
            }
#pragma unroll
            for (int i = 0; i < TM; i++)
#pragma unroll
                for (int j = 0; j < TN; j++)
                    acc[i][j] = fmaf(a[i], b[j], acc[i][j]);
        }
        __syncthreads();
    }

#pragma unroll
    for (int i = 0; i < TM; i++) {
        int row = m0 + (i/4)*(BM/2) + trow*4 + (i%4);
#pragma unroll
        for (int j = 0; j < TN; j++) {
            int col = n0 + (j/4)*(BN/2) + tcol*4 + (j%4);
            if (col < N) {
                size_t idx = (size_t)row * N + col;
                float v = acc[i][j];
                if (RESID) v += R[idx];
                C[idx] = v;
            }
        }
    }
}

// -------------------- causal depthwise conv (k=4) + bias + silu -------------
__global__ void conv_silu_kernel(const float* __restrict__ xz,
                                 const float* __restrict__ cw,
                                 const float* __restrict__ cb,
                                 float* __restrict__ xin) {
    int idx = blockIdx.x * blockDim.x + threadIdx.x;
    if (idx >= MTOT * DINNER) return;
    int e = idx % DINNER;
    int m = idx / DINNER;
    int l = m % SEQ;
    const float* xp = xz + (size_t)m * TWOE + e;
    float s = cb[e];
    float w0 = cw[e*4+0], w1 = cw[e*4+1], w2 = cw[e*4+2], w3 = cw[e*4+3];
    s = fmaf(w3, xp[0], s);
    if (l >= 1) s = fmaf(w2, xp[-(ptrdiff_t)TWOE], s);
    if (l >= 2) s = fmaf(w1, xp[-(ptrdiff_t)(2*TWOE)], s);
    if (l >= 3) s = fmaf(w0, xp[-(ptrdiff_t)(3*TWOE)], s);
    float sig = 1.f / (1.f + __expf(-s));
    xin[idx] = s * sig;
}

// -------------------- dt projection + softplus ------------------------------
__global__ void dtproj_kernel(const float* __restrict__ proj,
                              const float* __restrict__ dtw,
                              const float* __restrict__ dtb,
                              float* __restrict__ dt) {
    int idx = blockIdx.x * blockDim.x + threadIdx.x;
    if (idx >= MTOT * DINNER) return;
    int e = idx % DINNER;
    int m = idx / DINNER;
    const float* p = proj + (size_t)m * PROJC;   // first 24 cols = dt-rank part
    const float* w = dtw + (size_t)e * DTRANK;
    float s = dtb[e];
#pragma unroll
    for (int r = 0; r < DTRANK; r++) s = fmaf(p[r], w[r], s);
    dt[idx] = (s > 20.f) ? s : log1pf(__expf(s));
}

// -------------------- selective scan ----------------------------------------
// warp = 2 channels; lanes 0..15 -> states of channel e0, lanes 16..31 -> e1.
__global__ void scan_kernel(const float* __restrict__ dt,
                            const float* __restrict__ xin,
                            const float* __restrict__ proj,
                            const float* __restrict__ A_log,
                            float* __restrict__ ys) {
    int g    = (blockIdx.x * blockDim.x + threadIdx.x) >> 5;   // global warp
    int lane = threadIdx.x & 31;
    int b    = g / (DINNER/2);
    int pair = g % (DINNER/2);
    int e    = pair * 2 + (lane >> 4);
    int n    = lane & 15;

    float Aen = -__expf(A_log[(size_t)e * DSTATE + n]);

    size_t mb = (size_t)b * SEQ;
    const float* dtp = dt   + mb * DINNER + e;
    const float* xp  = xin  + mb * DINNER + e;
    const float* Bp  = proj + mb * PROJC + DTRANK + n;
    const float* Cp  = proj + mb * PROJC + DTRANK + DSTATE + n;
    float*       yp  = ys   + mb * DINNER + e;

    float h = 0.f;
#pragma unroll 4
    for (int tstep = 0; tstep < SEQ; tstep++) {
        float dtv = __ldg(dtp); dtp += DINNER;
        float xv  = __ldg(xp);  xp  += DINNER;
        float Bv  = __ldg(Bp);  Bp  += PROJC;
        float Cv  = __ldg(Cp);  Cp  += PROJC;
        float w = __expf(dtv * Aen);
        h = fmaf(h, w, dtv * xv * Bv);
        float p = h * Cv;
        p += __shfl_xor_sync(0xffffffffu, p, 1);
        p += __shfl_xor_sync(0xffffffffu, p, 2);
        p += __shfl_xor_sync(0xffffffffu, p, 4);
        p += __shfl_xor_sync(0xffffffffu, p, 8);
        if (n == 0) *yp = p;
        yp += DINNER;
    }
}

// -------------------- gate: y = (ys + xin*D) * silu(z) ----------------------
__global__ void gate_kernel(const float* __restrict__ ys,
                            const float* __restrict__ xin,
                            const float* __restrict__ xz,
                            const float* __restrict__ Dp,
                            float* __restrict__ y) {
    int idx = blockIdx.x * blockDim.x + threadIdx.x;
    if (idx >= MTOT * DINNER) return;
    int e = idx % DINNER;
    int m = idx / DINNER;
    float z = xz[(size_t)m * TWOE + DINNER + e];
    float sil = z / (1.f + __expf(-z));
    y[idx] = (ys[idx] + xin[idx] * Dp[e]) * sil;
}

// ---------------------------------------------------------------------------
extern "C" void kernel_launch(void* const* d_in, const int* in_sizes, int n_in,
                              void* d_out, int out_size) {
    (void)in_sizes; (void)n_in; (void)out_size;
    const int*   tokens  = (const int*)  d_in[0];
    const float* embed   = (const float*)d_in[1];
    const float* norm_w  = (const float*)d_in[2];
    const float* in_w    = (const float*)d_in[3];
    const float* conv_w  = (const float*)d_in[4];
    const float* conv_b  = (const float*)d_in[5];
    const float* xp_w    = (const float*)d_in[6];
    const float* dt_w    = (const float*)d_in[7];
    const float* dt_b    = (const float*)d_in[8];
    const float* A_log   = (const float*)d_in[9];
    const float* D_param = (const float*)d_in[10];
    const float* out_w   = (const float*)d_in[11];
    const float* fnorm_w = (const float*)d_in[12];
    float* out = (float*)d_out;

    float *px, *pxn, *pxz, *pxin, *pproj, *pdt, *pys, *py;
    cudaGetSymbolAddress((void**)&px,   g_x);
    cudaGetSymbolAddress((void**)&pxn,  g_xn);
    cudaGetSymbolAddress((void**)&pxz,  g_xz);
    cudaGetSymbolAddress((void**)&pxin, g_xin);
    cudaGetSymbolAddress((void**)&pproj,g_proj);
    cudaGetSymbolAddress((void**)&pdt,  g_dt);
    cudaGetSymbolAddress((void**)&pys,  g_ys);
    cudaGetSymbolAddress((void**)&py,   g_y);

    const int EW = MTOT * DINNER;            // 6291456
    const int EWB = (EW + 255) / 256;        // 24576
    const int GW = (MTOT * DMODEL + 255) / 256;

    embed_gather_kernel<<<GW, 256>>>(tokens, embed, px);

    for (int i = 0; i < NLAYER; i++) {
        rmsnorm_kernel<<<MTOT/8, dim3(32,8)>>>(px, norm_w + i*DMODEL, pxn);

        sgemm_kernel<128,128,8,8,8,false><<<dim3(TWOE/128, MTOT/128), 256>>>(
            pxn, in_w + (size_t)i*TWOE*DMODEL, pxz, nullptr, MTOT, TWOE, DMODEL);

        conv_silu_kernel<<<EWB, 256>>>(pxz, conv_w + i*DINNER*4, conv_b + i*DINNER, pxin);

        sgemm_kernel<64,64,16,4,4,false><<<dim3(1, MTOT/64), 256>>>(
            pxin, xp_w + (size_t)i*PROJC*DINNER, pproj, nullptr, MTOT, PROJC, DINNER);

        dtproj_kernel<<<EWB, 256>>>(pproj, dt_w + (size_t)i*DINNER*DTRANK,
                                    dt_b + i*DINNER, pdt);

        scan_kernel<<<(BATCHN*DINNER/2)/8, 256>>>(pdt, pxin, pproj,
                                                  A_log + (size_t)i*DINNER*DSTATE, pys);

        gate_kernel<<<EWB, 256>>>(pys, pxin, pxz, D_param + i*DINNER, py);

        sgemm_kernel<128,128,8,8,8,true><<<dim3(DMODEL/128, MTOT/128), 256>>>(
            py, out_w + (size_t)i*DMODEL*DINNER, px, px, MTOT, DMODEL, DINNER);
    }

    rmsnorm_kernel<<<MTOT/8, dim3(32,8)>>>(px, fnorm_w, pxn);

    sgemm_kernel<128,128,8,8,8,false><<<dim3((VOCABN+127)/128, MTOT/128), 256>>>(
        pxn, embed, out, nullptr, MTOT, VOCABN, DMODEL);
}

// round 11
// speedup vs baseline: 1.3343x; 1.3343x over previous
#include <cuda_runtime.h>
#include <cuda_bf16.h>
#include <cstdint>
#include <cstddef>

// ---------------------------------------------------------------------------
// Mamba-1 LM forward. Big GEMMs via mma.sync bf16 (sm_80 path — the harness
// compiles with virtual arch compute_103, which blocks all 'a'-gated features
// like tcgen05/TMA; mma.sync is the fastest available tensor-core route).
// Split precision: C = Ahi*Whi + Alo*Whi + Ahi*Wlo  (fp32-accurate).
// ---------------------------------------------------------------------------

#define BATCHN 4
#define SEQ    2048
#define DMODEL 384
#define NLAYER 4
#define VOCABN 5000
#define VOCPAD 5120
#define DINNER 768
#define DSTATE 16
#define DTRANK 24
#define PROJC  (DTRANK + 2*DSTATE)   // 56
#define MTOT   (BATCHN*SEQ)          // 8192
#define TWOE   (2*DINNER)            // 1536

// -------------------- scratch (static device globals, no allocs) -----------
__device__ float g_x  [MTOT*DMODEL];
__device__ float g_xz [MTOT*TWOE];
__device__ float g_xin[MTOT*DINNER];
__device__ float g_proj[MTOT*PROJC];
__device__ float g_dt [MTOT*DINNER];
__device__ float g_ys [MTOT*DINNER];
// bf16 split planes (activations)
__device__ __nv_bfloat16 g_xn_h[MTOT*DMODEL], g_xn_l[MTOT*DMODEL];
__device__ __nv_bfloat16 g_y_h [MTOT*DINNER], g_y_l [MTOT*DINNER];
// bf16 split planes (weights, converted every launch — deterministic)
__device__ __nv_bfloat16 g_wi_h[NLAYER*TWOE*DMODEL], g_wi_l[NLAYER*TWOE*DMODEL];
__device__ __nv_bfloat16 g_wo_h[NLAYER*DMODEL*DINNER], g_wo_l[NLAYER*DMODEL*DINNER];
__device__ __nv_bfloat16 g_we_h[VOCPAD*DMODEL], g_we_l[VOCPAD*DMODEL];

// -------------------- split helpers -----------------------------------------
__device__ __forceinline__ void fsplit(float v, __nv_bfloat16& h, __nv_bfloat16& l) {
    h = __float2bfloat16(v);
    l = __float2bfloat16(v - __bfloat162float(h));
}

__global__ void split_kernel(const float* __restrict__ src,
                             __nv_bfloat16* __restrict__ hi,
                             __nv_bfloat16* __restrict__ lo, int n) {
    int i = blockIdx.x * blockDim.x + threadIdx.x;
    if (i >= n) return;
    fsplit(src[i], hi[i], lo[i]);
}

// embed: convert 5000x384 and zero-pad rows to 5120
__global__ void split_pad_kernel(const float* __restrict__ src,
                                 __nv_bfloat16* __restrict__ hi,
                                 __nv_bfloat16* __restrict__ lo) {
    int i = blockIdx.x * blockDim.x + threadIdx.x;
    if (i >= VOCPAD * DMODEL) return;
    int row = i / DMODEL;
    if (row < VOCABN) {
        fsplit(src[i], hi[i], lo[i]);
    } else {
        hi[i] = __float2bfloat16(0.f);
        lo[i] = __float2bfloat16(0.f);
    }
}

// -------------------- mma.sync bf16 macro ------------------------------------
#define MMA16816(d, a0,a1,a2,a3, b0,b1) \
  asm volatile("mma.sync.aligned.m16n8k16.row.col.f32.bf16.bf16.f32 " \
    "{%0,%1,%2,%3}, {%4,%5,%6,%7}, {%8,%9}, {%0,%1,%2,%3};" \
    : "+f"(d[0]), "+f"(d[1]), "+f"(d[2]), "+f"(d[3]) \
    : "r"(a0), "r"(a1), "r"(a2), "r"(a3), "r"(b0), "r"(b1))

// -------------------- tensor-core GEMM: C[M,N] = A[M,K]*W[N,K]^T (+resid) ---
// block 128x128, 8 warps of 64x32. K-stage 32, smem rows padded to 40 halves.
#define SROW 40

template<bool RESID, bool NGUARD>
__global__ __launch_bounds__(256, 2)
void mma_gemm_kernel(const __nv_bfloat16* __restrict__ Ah, const __nv_bfloat16* __restrict__ Al,
                     const __nv_bfloat16* __restrict__ Wh, const __nv_bfloat16* __restrict__ Wl,
                     float* __restrict__ C, const float* __restrict__ R,
                     int Nglob, int K) {
    __shared__ __nv_bfloat16 sAh[128*SROW], sAl[128*SROW], sWh[128*SROW], sWl[128*SROW];

    const int t    = threadIdx.x;
    const int lane = t & 31;
    const int w    = t >> 5;
    const int wr   = w >> 2;      // 0..1
    const int wc   = w & 3;       // 0..3
    const int m0   = blockIdx.y * 128;
    const int n0   = blockIdx.x * 128;

    float acc[4][4][4];
#pragma unroll
    for (int mi = 0; mi < 4; mi++)
#pragma unroll
        for (int ni = 0; ni < 4; ni++)
#pragma unroll
            for (int q = 0; q < 4; q++) acc[mi][ni][q] = 0.f;

    uint4 rb[8];
    const int row0 = t >> 2, seg0 = t & 3;               // i=0 slice
    const int row1 = (t + 256) >> 2, seg1 = t & 3;       // i=1 slice

    // prefetch stage 0
    {
        const int k0 = 0;
        rb[0] = *(const uint4*)&Ah[(size_t)(m0+row0)*K + k0 + seg0*8];
        rb[1] = *(const uint4*)&Ah[(size_t)(m0+row1)*K + k0 + seg1*8];
        rb[2] = *(const uint4*)&Al[(size_t)(m0+row0)*K + k0 + seg0*8];
        rb[3] = *(const uint4*)&Al[(size_t)(m0+row1)*K + k0 + seg1*8];
        rb[4] = *(const uint4*)&Wh[(size_t)(n0+row0)*K + k0 + seg0*8];
        rb[5] = *(const uint4*)&Wh[(size_t)(n0+row1)*K + k0 + seg1*8];
        rb[6] = *(const uint4*)&Wl[(size_t)(n0+row0)*K + k0 + seg0*8];
        rb[7] = *(const uint4*)&Wl[(size_t)(n0+row1)*K + k0 + seg1*8];
    }

    const int nst = K >> 5;
    for (int s = 0; s < nst; s++) {
        __syncthreads();
        *(uint4*)&sAh[row0*SROW + seg0*8] = rb[0];
        *(uint4*)&sAh[row1*SROW + seg1*8] = rb[1];
        *(uint4*)&sAl[row0*SROW + seg0*8] = rb[2];
        *(uint4*)&sAl[row1*SROW + seg1*8] = rb[3];
        *(uint4*)&sWh[row0*SROW + seg0*8] = rb[4];
        *(uint4*)&sWh[row1*SROW + seg1*8] = rb[5];
        *(uint4*)&sWl[row0*SROW + seg0*8] = rb[6];
        *(uint4*)&sWl[row1*SROW + seg1*8] = rb[7];
        __syncthreads();

        if (s + 1 < nst) {
            const int k0 = (s + 1) << 5;
            rb[0] = *(const uint4*)&Ah[(size_t)(m0+row0)*K + k0 + seg0*8];
            rb[1] = *(const uint4*)&Ah[(size_t)(m0+row1)*K + k0 + seg1*8];
            rb[2] = *(const uint4*)&Al[(size_t)(m0+row0)*K + k0 + seg0*8];
            rb[3] = *(const uint4*)&Al[(size_t)(m0+row1)*K + k0 + seg1*8];
            rb[4] = *(const uint4*)&Wh[(size_t)(n0+row0)*K + k0 + seg0*8];
            rb[5] = *(const uint4*)&Wh[(size_t)(n0+row1)*K + k0 + seg1*8];
            rb[6] = *(const uint4*)&Wl[(size_t)(n0+row0)*K + k0 + seg0*8];
            rb[7] = *(const uint4*)&Wl[(size_t)(n0+row1)*K + k0 + seg1*8];
        }

#pragma unroll
        for (int st = 0; st < 2; st++) {
            const int kk = st * 16 + (lane & 3) * 2;
            uint32_t bh0[4], bh1[4], bl0[4], bl1[4];
#pragma unroll
            for (int ni = 0; ni < 4; ni++) {
                int nrow = wc*32 + ni*8 + (lane >> 2);
                int base = nrow*SROW + kk;
                bh0[ni] = *(const uint32_t*)&sWh[base];
                bh1[ni] = *(const uint32_t*)&sWh[base + 8];
                bl0[ni] = *(const uint32_t*)&sWl[base];
                bl1[ni] = *(const uint32_t*)&sWl[base + 8];
            }
#pragma unroll
            for (int mi = 0; mi < 4; mi++) {
                int r    = wr*64 + mi*16 + (lane >> 2);
                int base = r*SROW + kk;
                uint32_t ah0 = *(const uint32_t*)&sAh[base];
                uint32_t ah1 = *(const uint32_t*)&sAh[base + 8*SROW];
                uint32_t ah2 = *(const uint32_t*)&sAh[base + 8];
                uint32_t ah3 = *(const uint32_t*)&sAh[base + 8*SROW + 8];
                uint32_t al0 = *(const uint32_t*)&sAl[base];
                uint32_t al1 = *(const uint32_t*)&sAl[base + 8*SROW];
                uint32_t al2 = *(const uint32_t*)&sAl[base + 8];
                uint32_t al3 = *(const uint32_t*)&sAl[base + 8*SROW + 8];
#pragma unroll
                for (int ni = 0; ni < 4; ni++) {
                    MMA16816(acc[mi][ni], ah0, ah1, ah2, ah3, bh0[ni], bh1[ni]);
                    MMA16816(acc[mi][ni], al0, al1, al2, al3, bh0[ni], bh1[ni]);
                    MMA16816(acc[mi][ni], ah0, ah1, ah2, ah3, bl0[ni], bl1[ni]);
                }
            }
        }
    }

    // ---- epilogue ----
#pragma unroll
    for (int mi = 0; mi < 4; mi++) {
        int r = m0 + wr*64 + mi*16 + (lane >> 2);
#pragma unroll
        for (int ni = 0; ni < 4; ni++) {
            int col = n0 + wc*32 + ni*8 + (lane & 3)*2;
            if (!NGUARD || col < Nglob) {
                size_t i0 = (size_t)r * Nglob + col;
                size_t i1 = (size_t)(r + 8) * Nglob + col;
                float2 v0 = make_float2(acc[mi][ni][0], acc[mi][ni][1]);
                float2 v1 = make_float2(acc[mi][ni][2], acc[mi][ni][3]);
                if (RESID) {
                    v0.x += R[i0]; v0.y += R[i0+1];
                    v1.x += R[i1]; v1.y += R[i1+1];
                }
                *(float2*)&C[i0] = v0;
                *(float2*)&C[i1] = v1;
            }
        }
    }
}

// -------------------- embedding gather -------------------------------------
__global__ void embed_gather_kernel(const int* __restrict__ tok,
                                    const float* __restrict__ emb,
                                    float* __restrict__ x) {
    int idx = blockIdx.x * blockDim.x + threadIdx.x;
    if (idx >= MTOT * DMODEL) return;
    int m = idx / DMODEL;
    int d = idx - m * DMODEL;
    x[idx] = emb[(size_t)tok[m] * DMODEL + d];
}

// -------------------- rmsnorm -> bf16 hi/lo planes --------------------------
__global__ void rmsnorm_kernel(const float* __restrict__ x,
                               const float* __restrict__ w,
                               __nv_bfloat16* __restrict__ oh,
                               __nv_bfloat16* __restrict__ ol) {
    int row  = blockIdx.x * blockDim.y + threadIdx.y;
    int lane = threadIdx.x;
    const float* xr = x + (size_t)row * DMODEL;
    float v[12];
    float ss = 0.f;
#pragma unroll
    for (int i = 0; i < 12; i++) { v[i] = xr[lane + i*32]; ss = fmaf(v[i], v[i], ss); }
#pragma unroll
    for (int off = 16; off > 0; off >>= 1)
        ss += __shfl_xor_sync(0xffffffffu, ss, off);
    float sc = rsqrtf(ss * (1.0f/DMODEL) + 1e-5f);
#pragma unroll
    for (int i = 0; i < 12; i++) {
        float val = v[i] * sc * w[lane + i*32];
        size_t o = (size_t)row * DMODEL + lane + i*32;
        __nv_bfloat16 h, l;
        fsplit(val, h, l);
        oh[o] = h; ol[o] = l;
    }
}

// -------------------- small fp32 SGEMM for x_proj ---------------------------
template<int BM, int BN, int BK, int TM, int TN>
__global__ __launch_bounds__((BM/TM)*(BN/TN))
void sgemm_kernel(const float* __restrict__ A, const float* __restrict__ W,
                  float* __restrict__ C, int M, int N, int K) {
    constexpr int KG = BK / 4;
    __shared__ float As[BK][BM + 4];
    __shared__ float Bs[BK][BN + 4];

    const int t  = threadIdx.x;
    const int m0 = blockIdx.y * BM;
    const int n0 = blockIdx.x * BN;

    const int lrow = t / KG;
    const int lk   = (t % KG) * 4;

    const float* Ap = A + (size_t)(m0 + lrow) * K + lk;
    const int   wrow = n0 + lrow;
    const bool  wv   = wrow < N;
    const float* Wp  = W + (size_t)wrow * K + lk;

    float4 ra = *(const float4*)Ap;
    float4 rb = wv ? *(const float4*)Wp : make_float4(0.f,0.f,0.f,0.f);

    const int trow = t / (BN/TN);
    const int tcol = t % (BN/TN);

    float acc[TM][TN];
#pragma unroll
    for (int i = 0; i < TM; i++)
#pragma unroll
        for (int j = 0; j < TN; j++) acc[i][j] = 0.f;

    const int nK = K / BK;
    for (int kt = 0; kt < nK; kt++) {
        As[lk+0][lrow] = ra.x; As[lk+1][lrow] = ra.y;
        As[lk+2][lrow] = ra.z; As[lk+3][lrow] = ra.w;
        Bs[lk+0][lrow] = rb.x; Bs[lk+1][lrow] = rb.y;
        Bs[lk+2][lrow] = rb.z; Bs[lk+3][lrow] = rb.w;
        __syncthreads();

        if (kt + 1 < nK) {
            Ap += BK; Wp += BK;
            ra = *(const float4*)Ap;
            rb = wv ? *(const float4*)Wp : make_float4(0.f,0.f,0.f,0.f);
        }

#pragma unroll
        for (int kk = 0; kk < BK; kk++) {
            float a[TM], b[TN];
#pragma unroll
            for (int h = 0; h < TM/4; h++) {
                float4 v = *(const float4*)&As[kk][h*(BM/2) + trow*4];
                a[h*4+0]=v.x; a[h*4+1]=v.y; a[h*4+2]=v.z; a[h*4+3]=v.w;
            }
#pragma unroll
            for (int h = 0; h < TN/4; h++) {
                float4 v = *(const float4*)&Bs[kk][h*(BN/2) + tcol*4];
                b[h*4+0]=v.x; b[h*4+1]=v.y; b[h*4+2]=v.z; b[h*4+3]=v.w;
            }
#pragma unroll
            for (int i = 0; i < TM; i++)
#pragma unroll
                for (int j = 0; j < TN; j++)
                    acc[i][j] = fmaf(a[i], b[j], acc[i][j]);
        }
        __syncthreads();
    }

#pragma unroll
    for (int i = 0; i < TM; i++) {
        int row = m0 + (i/4)*(BM/2) + trow*4 + (i%4);
#pragma unroll
        for (int j = 0; j < TN; j++) {
            int col = n0 + (j/4)*(BN/2) + tcol*4 + (j%4);
            if (col < N) C[(size_t)row * N + col] = acc[i][j];
        }
    }
}

// -------------------- causal depthwise conv (k=4) + bias + silu -------------
__global__ void conv_silu_kernel(const float* __restrict__ xz,
                                 const float* __restrict__ cw,
                                 const float* __restrict__ cb,
                                 float* __restrict__ xin) {
    int idx = blockIdx.x * blockDim.x + threadIdx.x;
    if (idx >= MTOT * DINNER) return;
    int e = idx % DINNER;
    int m = idx / DINNER;
    int l = m % SEQ;
    const float* xp = xz + (size_t)m * TWOE + e;
    float s = cb[e];
    float w0 = cw[e*4+0], w1 = cw[e*4+1], w2 = cw[e*4+2], w3 = cw[e*4+3];
    s = fmaf(w3, xp[0], s);
    if (l >= 1) s = fmaf(w2, xp[-(ptrdiff_t)TWOE], s);
    if (l >= 2) s = fmaf(w1, xp[-(ptrdiff_t)(2*TWOE)], s);
    if (l >= 3) s = fmaf(w0, xp[-(ptrdiff_t)(3*TWOE)], s);
    float sig = 1.f / (1.f + __expf(-s));
    xin[idx] = s * sig;
}

// -------------------- dt projection + softplus ------------------------------
__global__ void dtproj_kernel(const float* __restrict__ proj,
                              const float* __restrict__ dtw,
                              const float* __restrict__ dtb,
                              float* __restrict__ dt) {
    int idx = blockIdx.x * blockDim.x + threadIdx.x;
    if (idx >= MTOT * DINNER) return;
    int e = idx % DINNER;
    int m = idx / DINNER;
    const float* p = proj + (size_t)m * PROJC;
    const float* w = dtw + (size_t)e * DTRANK;
    float s = dtb[e];
#pragma unroll
    for (int r = 0; r < DTRANK; r++) s = fmaf(p[r], w[r], s);
    dt[idx] = (s > 20.f) ? s : log1pf(__expf(s));
}

// -------------------- selective scan ----------------------------------------
__global__ void scan_kernel(const float* __restrict__ dt,
                            const float* __restrict__ xin,
                            const float* __restrict__ proj,
                            const float* __restrict__ A_log,
                            float* __restrict__ ys) {
    int g    = (blockIdx.x * blockDim.x + threadIdx.x) >> 5;
    int lane = threadIdx.x & 31;
    int b    = g / (DINNER/2);
    int pair = g % (DINNER/2);
    int e    = pair * 2 + (lane >> 4);
    int n    = lane & 15;

    float Aen = -__expf(A_log[(size_t)e * DSTATE + n]);

    size_t mb = (size_t)b * SEQ;
    const float* dtp = dt   + mb * DINNER + e;
    const float* xp  = xin  + mb * DINNER + e;
    const float* Bp  = proj + mb * PROJC + DTRANK + n;
    const float* Cp  = proj + mb * PROJC + DTRANK + DSTATE + n;
    float*       yp  = ys   + mb * DINNER + e;

    float h = 0.f;
#pragma unroll 4
    for (int tstep = 0; tstep < SEQ; tstep++) {
        float dtv = __ldg(dtp); dtp += DINNER;
        float xv  = __ldg(xp);  xp  += DINNER;
        float Bv  = __ldg(Bp);  Bp  += PROJC;
        float Cv  = __ldg(Cp);  Cp  += PROJC;
        float w = __expf(dtv * Aen);
        h = fmaf(h, w, dtv * xv * Bv);
        float p = h * Cv;
        p += __shfl_xor_sync(0xffffffffu, p, 1);
        p += __shfl_xor_sync(0xffffffffu, p, 2);
        p += __shfl_xor_sync(0xffffffffu, p, 4);
        p += __shfl_xor_sync(0xffffffffu, p, 8);
        if (n == 0) *yp = p;
        yp += DINNER;
    }
}

// -------------------- gate -> bf16 hi/lo planes -----------------------------
__global__ void gate_kernel(const float* __restrict__ ys,
                            const float* __restrict__ xin,
                            const float* __restrict__ xz,
                            const float* __restrict__ Dp,
                            __nv_bfloat16* __restrict__ yh,
                            __nv_bfloat16* __restrict__ yl) {
    int idx = blockIdx.x * blockDim.x + threadIdx.x;
    if (idx >= MTOT * DINNER) return;
    int e = idx % DINNER;
    int m = idx / DINNER;
    float z = xz[(size_t)m * TWOE + DINNER + e];
    float sil = z / (1.f + __expf(-z));
    float v = (ys[idx] + xin[idx] * Dp[e]) * sil;
    __nv_bfloat16 h, l;
    fsplit(v, h, l);
    yh[idx] = h; yl[idx] = l;
}

// ---------------------------------------------------------------------------
extern "C" void kernel_launch(void* const* d_in, const int* in_sizes, int n_in,
                              void* d_out, int out_size) {
    (void)in_sizes; (void)n_in; (void)out_size;
    const int*   tokens  = (const int*)  d_in[0];
    const float* embed   = (const float*)d_in[1];
    const float* norm_w  = (const float*)d_in[2];
    const float* in_w    = (const float*)d_in[3];
    const float* conv_w  = (const float*)d_in[4];
    const float* conv_b  = (const float*)d_in[5];
    const float* xp_w    = (const float*)d_in[6];
    const float* dt_w    = (const float*)d_in[7];
    const float* dt_b    = (const float*)d_in[8];
    const float* A_log   = (const float*)d_in[9];
    const float* D_param = (const float*)d_in[10];
    const float* out_w   = (const float*)d_in[11];
    const float* fnorm_w = (const float*)d_in[12];
    float* out = (float*)d_out;

    float *px, *pxz, *pxin, *pproj, *pdt, *pys;
    __nv_bfloat16 *pxnh, *pxnl, *pyh, *pyl, *pwih, *pwil, *pwoh, *pwol, *pweh, *pwel;
    cudaGetSymbolAddress((void**)&px,   g_x);
    cudaGetSymbolAddress((void**)&pxz,  g_xz);
    cudaGetSymbolAddress((void**)&pxin, g_xin);
    cudaGetSymbolAddress((void**)&pproj,g_proj);
    cudaGetSymbolAddress((void**)&pdt,  g_dt);
    cudaGetSymbolAddress((void**)&pys,  g_ys);
    cudaGetSymbolAddress((void**)&pxnh, g_xn_h);
    cudaGetSymbolAddress((void**)&pxnl, g_xn_l);
    cudaGetSymbolAddress((void**)&pyh,  g_y_h);
    cudaGetSymbolAddress((void**)&pyl,  g_y_l);
    cudaGetSymbolAddress((void**)&pwih, g_wi_h);
    cudaGetSymbolAddress((void**)&pwil, g_wi_l);
    cudaGetSymbolAddress((void**)&pwoh, g_wo_h);
    cudaGetSymbolAddress((void**)&pwol, g_wo_l);
    cudaGetSymbolAddress((void**)&pweh, g_we_h);
    cudaGetSymbolAddress((void**)&pwel, g_we_l);

    const int EW  = MTOT * DINNER;
    const int EWB = (EW + 255) / 256;
    const int GW  = (MTOT * DMODEL + 255) / 256;

    // weight splits (every launch; deterministic)
    {
        int n1 = NLAYER * TWOE * DMODEL;
        split_kernel<<<(n1 + 255)/256, 256>>>(in_w, pwih, pwil, n1);
        int n2 = NLAYER * DMODEL * DINNER;
        split_kernel<<<(n2 + 255)/256, 256>>>(out_w, pwoh, pwol, n2);
        int n3 = VOCPAD * DMODEL;
        split_pad_kernel<<<(n3 + 255)/256, 256>>>(embed, pweh, pwel);
    }

    embed_gather_kernel<<<GW, 256>>>(tokens, embed, px);

    for (int i = 0; i < NLAYER; i++) {
        rmsnorm_kernel<<<MTOT/8, dim3(32,8)>>>(px, norm_w + i*DMODEL, pxnh, pxnl);

        // in_proj: [8192,384] x [1536,384]^T -> [8192,1536]
        mma_gemm_kernel<false,false><<<dim3(TWOE/128, MTOT/128), 256>>>(
            pxnh, pxnl, pwih + (size_t)i*TWOE*DMODEL, pwil + (size_t)i*TWOE*DMODEL,
            pxz, nullptr, TWOE, DMODEL);

        conv_silu_kernel<<<EWB, 256>>>(pxz, conv_w + i*DINNER*4, conv_b + i*DINNER, pxin);

        sgemm_kernel<64,64,16,4,4><<<dim3(1, MTOT/64), 256>>>(
            pxin, xp_w + (size_t)i*PROJC*DINNER, pproj, MTOT, PROJC, DINNER);

        dtproj_kernel<<<EWB, 256>>>(pproj, dt_w + (size_t)i*DINNER*DTRANK,
                                    dt_b + i*DINNER, pdt);

        scan_kernel<<<(BATCHN*DINNER/2)/8, 256>>>(pdt, pxin, pproj,
                                                  A_log + (size_t)i*DINNER*DSTATE, pys);

        gate_kernel<<<EWB, 256>>>(pys, pxin, pxz, D_param + i*DINNER, pyh, pyl);

        // out_proj (+residual): [8192,768] x [384,768]^T -> [8192,384]
        mma_gemm_kernel<true,false><<<dim3(DMODEL/128, MTOT/128), 256>>>(
            pyh, pyl, pwoh + (size_t)i*DMODEL*DINNER, pwol + (size_t)i*DMODEL*DINNER,
            px, px, DMODEL, DINNER);
    }

    rmsnorm_kernel<<<MTOT/8, dim3(32,8)>>>(px, fnorm_w, pxnh, pxnl);

    // lm_head: [8192,384] x [5000,384]^T -> [8192,5000] (W padded to 5120 rows)
    mma_gemm_kernel<false,true><<<dim3(VOCPAD/128, MTOT/128), 256>>>(
        pxnh, pxnl, pweh, pwel, out, nullptr, VOCABN, DMODEL);
}

// round 16
// speedup vs baseline: 1.3735x; 1.0293x over previous
#include <cuda_runtime.h>
#include <cuda_bf16.h>
#include <cstdint>
#include <cstddef>

// ---------------------------------------------------------------------------
// Mamba-1 LM forward. Big GEMMs via mma.sync bf16 (compute_103 blocks all
// 'a'-gated features: tcgen05/TMA). Split precision 3-MMA, ldmatrix + cp.async.
// ---------------------------------------------------------------------------

#define BATCHN 4
#define SEQ    2048
#define DMODEL 384
#define NLAYER 4
#define VOCABN 5000
#define VOCPAD 5120
#define DINNER 768
#define DSTATE 16
#define DTRANK 24
#define PROJC  (DTRANK + 2*DSTATE)   // 56
#define MTOT   (BATCHN*SEQ)          // 8192
#define TWOE   (2*DINNER)            // 1536

// -------------------- scratch (static device globals, no allocs) -----------
__device__ float g_x  [MTOT*DMODEL];
__device__ float g_xz [MTOT*TWOE];
__device__ float g_xin[MTOT*DINNER];
__device__ float g_proj[MTOT*PROJC];
__device__ float g_dt [MTOT*DINNER];
__device__ float g_ys [MTOT*DINNER];
__device__ __nv_bfloat16 g_xn_h[MTOT*DMODEL], g_xn_l[MTOT*DMODEL];
__device__ __nv_bfloat16 g_y_h [MTOT*DINNER], g_y_l [MTOT*DINNER];
__device__ __nv_bfloat16 g_wi_h[NLAYER*TWOE*DMODEL], g_wi_l[NLAYER*TWOE*DMODEL];
__device__ __nv_bfloat16 g_wo_h[NLAYER*DMODEL*DINNER], g_wo_l[NLAYER*DMODEL*DINNER];
__device__ __nv_bfloat16 g_we_h[VOCPAD*DMODEL], g_we_l[VOCPAD*DMODEL];

// -------------------- split helpers -----------------------------------------
__device__ __forceinline__ void fsplit(float v, __nv_bfloat16& h, __nv_bfloat16& l) {
    h = __float2bfloat16(v);
    l = __float2bfloat16(v - __bfloat162float(h));
}

__global__ void split_kernel(const float* __restrict__ src,
                             __nv_bfloat16* __restrict__ hi,
                             __nv_bfloat16* __restrict__ lo, int n) {
    int i = blockIdx.x * blockDim.x + threadIdx.x;
    if (i >= n) return;
    fsplit(src[i], hi[i], lo[i]);
}

__global__ void split_pad_kernel(const float* __restrict__ src,
                                 __nv_bfloat16* __restrict__ hi,
                                 __nv_bfloat16* __restrict__ lo) {
    int i = blockIdx.x * blockDim.x + threadIdx.x;
    if (i >= VOCPAD * DMODEL) return;
    int row = i / DMODEL;
    if (row < VOCABN) {
        fsplit(src[i], hi[i], lo[i]);
    } else {
        hi[i] = __float2bfloat16(0.f);
        lo[i] = __float2bfloat16(0.f);
    }
}

// -------------------- PTX helpers -------------------------------------------
__device__ __forceinline__ uint32_t smem_u32(const void* p) {
    uint32_t a;
    asm("{ .reg .u64 t; cvta.to.shared.u64 t, %1; cvt.u32.u64 %0, t; }" : "=r"(a) : "l"(p));
    return a;
}

#define MMA16816(d, a0,a1,a2,a3, b0,b1) \
  asm volatile("mma.sync.aligned.m16n8k16.row.col.f32.bf16.bf16.f32 " \
    "{%0,%1,%2,%3}, {%4,%5,%6,%7}, {%8,%9}, {%0,%1,%2,%3};" \
    : "+f"(d[0]), "+f"(d[1]), "+f"(d[2]), "+f"(d[3]) \
    : "r"(a0), "r"(a1), "r"(a2), "r"(a3), "r"(b0), "r"(b1))

#define LDSM4(r0,r1,r2,r3, addr) \
  asm volatile("ldmatrix.sync.aligned.m8n8.x4.shared.b16 {%0,%1,%2,%3}, [%4];" \
    : "=r"(r0), "=r"(r1), "=r"(r2), "=r"(r3) : "r"(addr))

__device__ __forceinline__ void cp16(uint32_t saddr, const void* g) {
    asm volatile("cp.async.cg.shared.global [%0], [%1], 16;" :: "r"(saddr), "l"(g) : "memory");
}
#define CP_COMMIT() asm volatile("cp.async.commit_group;" ::: "memory")
#define CP_WAIT(n)  asm volatile("cp.async.wait_group " #n ";" ::: "memory")

// -------------------- tensor-core GEMM: C[M,N] = A[M,K]*W[N,K]^T (+resid) ---
// block 128x128, 8 warps of 64x32. K-stage 32 halves; smem row = 40 halves (80B).
// 2-stage cp.async ring; ldmatrix.x4 fragments; 3-MMA split precision.
#define SROWB   80                    // bytes per smem row
#define PLANEB  (128*SROWB)           // 10240 B
#define STAGEB  (4*PLANEB)            // 40960 B
#define GSMEM   (2*STAGEB)            // 81920 B

template<bool RESID, bool NGUARD>
__global__ __launch_bounds__(256)
void mma_gemm_kernel(const __nv_bfloat16* __restrict__ Ah, const __nv_bfloat16* __restrict__ Al,
                     const __nv_bfloat16* __restrict__ Wh, const __nv_bfloat16* __restrict__ Wl,
                     float* __restrict__ C, const float* __restrict__ R,
                     int Nglob, int K) {
    extern __shared__ char dsm[];
    const uint32_t sbase = smem_u32(dsm);

    const int t    = threadIdx.x;
    const int lane = t & 31;
    const int w    = t >> 5;
    const int wr   = w >> 2;      // 0..1
    const int wc   = w & 3;       // 0..3
    const int m0   = blockIdx.y * 128;
    const int n0   = blockIdx.x * 128;

    // fill mapping: two 16B segments per plane per thread
    const int row0 = t >> 2, seg0 = t & 3;
    const int row1 = (t + 256) >> 2, seg1 = t & 3;

    const __nv_bfloat16* gp[4] = { Ah, Al, Wh, Wl };
    const int grow0[4] = { m0+row0, m0+row0, n0+row0, n0+row0 };
    const int grow1[4] = { m0+row1, m0+row1, n0+row1, n0+row1 };

    float acc[4][4][4];
#pragma unroll
    for (int mi = 0; mi < 4; mi++)
#pragma unroll
        for (int ni = 0; ni < 4; ni++)
#pragma unroll
            for (int q = 0; q < 4; q++) acc[mi][ni][q] = 0.f;

    const int nst = K >> 5;

    // prologue: stage 0
    {
        const int k0 = 0;
        uint32_t sb = sbase;
#pragma unroll
        for (int p = 0; p < 4; p++) {
            cp16(sb + p*PLANEB + row0*SROWB + seg0*16, gp[p] + (size_t)grow0[p]*K + k0 + seg0*8);
            cp16(sb + p*PLANEB + row1*SROWB + seg1*16, gp[p] + (size_t)grow1[p]*K + k0 + seg1*8);
        }
        CP_COMMIT();
    }

    // fragment ldmatrix lane addressing (byte offsets within a plane)
    const int arow = (lane & 15);                 // A: row within 16
    const int acol = (lane >> 4) * 16;            // A: +8 halves = +16B
    const int brow = (lane & 7) + ((lane & 16) ? 8 : 0);
    const int bcol = (lane & 8) ? 16 : 0;

    for (int s = 0; s < nst; s++) {
        if (s + 1 < nst) {
            const int k0 = (s + 1) << 5;
            uint32_t sb = sbase + ((s + 1) & 1) * STAGEB;
#pragma unroll
            for (int p = 0; p < 4; p++) {
                cp16(sb + p*PLANEB + row0*SROWB + seg0*16, gp[p] + (size_t)grow0[p]*K + k0 + seg0*8);
                cp16(sb + p*PLANEB + row1*SROWB + seg1*16, gp[p] + (size_t)grow1[p]*K + k0 + seg1*8);
            }
            CP_COMMIT();
            CP_WAIT(1);
        } else {
            CP_WAIT(0);
        }
        __syncthreads();

        const uint32_t buf = sbase + (s & 1) * STAGEB;
        const uint32_t bAh = buf;
        const uint32_t bAl = buf + PLANEB;
        const uint32_t bWh = buf + 2*PLANEB;
        const uint32_t bWl = buf + 3*PLANEB;

#pragma unroll
        for (int st = 0; st < 2; st++) {
            const int kb = st * 32;   // bytes: 16 halves per st
            // B fragments: 2 groups of 16 n-rows per plane
            uint32_t bh[4][2], bl[4][2];
#pragma unroll
            for (int g = 0; g < 2; g++) {
                uint32_t ro = (uint32_t)((wc*32 + g*16 + brow) * SROWB + kb + bcol);
                LDSM4(bh[2*g][0], bh[2*g][1], bh[2*g+1][0], bh[2*g+1][1], bWh + ro);
                LDSM4(bl[2*g][0], bl[2*g][1], bl[2*g+1][0], bl[2*g+1][1], bWl + ro);
            }
#pragma unroll
            for (int mi = 0; mi < 4; mi++) {
                uint32_t ro = (uint32_t)((wr*64 + mi*16 + arow) * SROWB + kb + acol);
                uint32_t ah0, ah1, ah2, ah3, al0, al1, al2, al3;
                LDSM4(ah0, ah1, ah2, ah3, bAh + ro);
                LDSM4(al0, al1, al2, al3, bAl + ro);
#pragma unroll
                for (int ni = 0; ni < 4; ni++) {
                    MMA16816(acc[mi][ni], ah0, ah1, ah2, ah3, bh[ni][0], bh[ni][1]);
                    MMA16816(acc[mi][ni], al0, al1, al2, al3, bh[ni][0], bh[ni][1]);
                    MMA16816(acc[mi][ni], ah0, ah1, ah2, ah3, bl[ni][0], bl[ni][1]);
                }
            }
        }
        __syncthreads();
    }

    // ---- epilogue ----
#pragma unroll
    for (int mi = 0; mi < 4; mi++) {
        int r = m0 + wr*64 + mi*16 + (lane >> 2);
#pragma unroll
        for (int ni = 0; ni < 4; ni++) {
            int col = n0 + wc*32 + ni*8 + (lane & 3)*2;
            if (!NGUARD || col < Nglob) {
                size_t i0 = (size_t)r * Nglob + col;
                size_t i1 = (size_t)(r + 8) * Nglob + col;
                float2 v0 = make_float2(acc[mi][ni][0], acc[mi][ni][1]);
                float2 v1 = make_float2(acc[mi][ni][2], acc[mi][ni][3]);
                if (RESID) {
                    v0.x += R[i0]; v0.y += R[i0+1];
                    v1.x += R[i1]; v1.y += R[i1+1];
                }
                *(float2*)&C[i0] = v0;
                *(float2*)&C[i1] = v1;
            }
        }
    }
}

// -------------------- embedding gather -------------------------------------
__global__ void embed_gather_kernel(const int* __restrict__ tok,
                                    const float* __restrict__ emb,
                                    float* __restrict__ x) {
    int idx = blockIdx.x * blockDim.x + threadIdx.x;
    if (idx >= MTOT * DMODEL) return;
    int m = idx / DMODEL;
    int d = idx - m * DMODEL;
    x[idx] = emb[(size_t)tok[m] * DMODEL + d];
}

// -------------------- rmsnorm -> bf16 hi/lo planes --------------------------
__global__ void rmsnorm_kernel(const float* __restrict__ x,
                               const float* __restrict__ w,
                               __nv_bfloat16* __restrict__ oh,
                               __nv_bfloat16* __restrict__ ol) {
    int row  = blockIdx.x * blockDim.y + threadIdx.y;
    int lane = threadIdx.x;
    const float* xr = x + (size_t)row * DMODEL;
    float v[12];
    float ss = 0.f;
#pragma unroll
    for (int i = 0; i < 12; i++) { v[i] = xr[lane + i*32]; ss = fmaf(v[i], v[i], ss); }
#pragma unroll
    for (int off = 16; off > 0; off >>= 1)
        ss += __shfl_xor_sync(0xffffffffu, ss, off);
    float sc = rsqrtf(ss * (1.0f/DMODEL) + 1e-5f);
#pragma unroll
    for (int i = 0; i < 12; i++) {
        float val = v[i] * sc * w[lane + i*32];
        size_t o = (size_t)row * DMODEL + lane + i*32;
        __nv_bfloat16 h, l;
        fsplit(val, h, l);
        oh[o] = h; ol[o] = l;
    }
}

// -------------------- small fp32 SGEMM for x_proj ---------------------------
template<int BM, int BN, int BK, int TM, int TN>
__global__ __launch_bounds__((BM/TM)*(BN/TN))
void sgemm_kernel(const float* __restrict__ A, const float* __restrict__ W,
                  float* __restrict__ C, int M, int N, int K) {
    constexpr int KG = BK / 4;
    __shared__ float As[BK][BM + 4];
    __shared__ float Bs[BK][BN + 4];

    const int t  = threadIdx.x;
    const int m0 = blockIdx.y * BM;
    const int n0 = blockIdx.x * BN;

    const int lrow = t / KG;
    const int lk   = (t % KG) * 4;

    const float* Ap = A + (size_t)(m0 + lrow) * K + lk;
    const int   wrow = n0 + lrow;
    const bool  wv   = wrow < N;
    const float* Wp  = W + (size_t)wrow * K + lk;

    float4 ra = *(const float4*)Ap;
    float4 rb = wv ? *(const float4*)Wp : make_float4(0.f,0.f,0.f,0.f);

    const int trow = t / (BN/TN);
    const int tcol = t % (BN/TN);

    float acc[TM][TN];
#pragma unroll
    for (int i = 0; i < TM; i++)
#pragma unroll
        for (int j = 0; j < TN; j++) acc[i][j] = 0.f;

    const int nK = K / BK;
    for (int kt = 0; kt < nK; kt++) {
        As[lk+0][lrow] = ra.x; As[lk+1][lrow] = ra.y;
        As[lk+2][lrow] = ra.z; As[lk+3][lrow] = ra.w;
        Bs[lk+0][lrow] = rb.x; Bs[lk+1][lrow] = rb.y;
        Bs[lk+2][lrow] = rb.z; Bs[lk+3][lrow] = rb.w;
        __syncthreads();

        if (kt + 1 < nK) {
            Ap += BK; Wp += BK;
            ra = *(const float4*)Ap;
            rb = wv ? *(const float4*)Wp : make_float4(0.f,0.f,0.f,0.f);
        }

#pragma unroll
        for (int kk = 0; kk < BK; kk++) {
            float a[TM], b[TN];
#pragma unroll
            for (int h = 0; h < TM/4; h++) {
                float4 v = *(const float4*)&As[kk][h*(BM/2) + trow*4];
                a[h*4+0]=v.x; a[h*4+1]=v.y; a[h*4+2]=v.z; a[h*4+3]=v.w;
            }
#pragma unroll
            for (int h = 0; h < TN/4; h++) {
                float4 v = *(const float4*)&Bs[kk][h*(BN/2) + tcol*4];
                b[h*4+0]=v.x; b[h*4+1]=v.y; b[h*4+2]=v.z; b[h*4+3]=v.w;
            }
#pragma unroll
            for (int i = 0; i < TM; i++)
#pragma unroll
                for (int j = 0; j < TN; j++)
                    acc[i][j] = fmaf(a[i], b[j], acc[i][j]);
        }
        __syncthreads();
    }

#pragma unroll
    for (int i = 0; i < TM; i++) {
        int row = m0 + (i/4)*(BM/2) + trow*4 + (i%4);
#pragma unroll
        for (int j = 0; j < TN; j++) {
            int col = n0 + (j/4)*(BN/2) + tcol*4 + (j%4);
            if (col < N) C[(size_t)row * N + col] = acc[i][j];
        }
    }
}

// -------------------- causal depthwise conv (k=4) + bias + silu -------------
__global__ void conv_silu_kernel(const float* __restrict__ xz,
                                 const float* __restrict__ cw,
                                 const float* __restrict__ cb,
                                 float* __restrict__ xin) {
    int idx = blockIdx.x * blockDim.x + threadIdx.x;
    if (idx >= MTOT * DINNER) return;
    int e = idx % DINNER;
    int m = idx / DINNER;
    int l = m % SEQ;
    const float* xp = xz + (size_t)m * TWOE + e;
    float s = cb[e];
    float w0 = cw[e*4+0], w1 = cw[e*4+1], w2 = cw[e*4+2], w3 = cw[e*4+3];
    s = fmaf(w3, xp[0], s);
    if (l >= 1) s = fmaf(w2, xp[-(ptrdiff_t)TWOE], s);
    if (l >= 2) s = fmaf(w1, xp[-(ptrdiff_t)(2*TWOE)], s);
    if (l >= 3) s = fmaf(w0, xp[-(ptrdiff_t)(3*TWOE)], s);
    float sig = 1.f / (1.f + __expf(-s));
    xin[idx] = s * sig;
}

// -------------------- dt projection + softplus ------------------------------
__global__ void dtproj_kernel(const float* __restrict__ proj,
                              const float* __restrict__ dtw,
                              const float* __restrict__ dtb,
                              float* __restrict__ dt) {
    int idx = blockIdx.x * blockDim.x + threadIdx.x;
    if (idx >= MTOT * DINNER) return;
    int e = idx % DINNER;
    int m = idx / DINNER;
    const float* p = proj + (size_t)m * PROJC;
    const float* w = dtw + (size_t)e * DTRANK;
    float s = dtb[e];
#pragma unroll
    for (int r = 0; r < DTRANK; r++) s = fmaf(p[r], w[r], s);
    dt[idx] = (s > 20.f) ? s : log1pf(__expf(s));
}

// -------------------- selective scan ----------------------------------------
__global__ void scan_kernel(const float* __restrict__ dt,
                            const float* __restrict__ xin,
                            const float* __restrict__ proj,
                            const float* __restrict__ A_log,
                            float* __restrict__ ys) {
    int g    = (blockIdx.x * blockDim.x + threadIdx.x) >> 5;
    int lane = threadIdx.x & 31;
    int b    = g / (DINNER/2);
    int pair = g % (DINNER/2);
    int e    = pair * 2 + (lane >> 4);
    int n    = lane & 15;

    float Aen = -__expf(A_log[(size_t)e * DSTATE + n]);

    size_t mb = (size_t)b * SEQ;
    const float* dtp = dt   + mb * DINNER + e;
    const float* xp  = xin  + mb * DINNER + e;
    const float* Bp  = proj + mb * PROJC + DTRANK + n;
    const float* Cp  = proj + mb * PROJC + DTRANK + DSTATE + n;
    float*       yp  = ys   + mb * DINNER + e;

    float h = 0.f;
#pragma unroll 4
    for (int tstep = 0; tstep < SEQ; tstep++) {
        float dtv = __ldg(dtp); dtp += DINNER;
        float xv  = __ldg(xp);  xp  += DINNER;
        float Bv  = __ldg(Bp);  Bp  += PROJC;
        float Cv  = __ldg(Cp);  Cp  += PROJC;
        float w = __expf(dtv * Aen);
        h = fmaf(h, w, dtv * xv * Bv);
        float p = h * Cv;
        p += __shfl_xor_sync(0xffffffffu, p, 1);
        p += __shfl_xor_sync(0xffffffffu, p, 2);
        p += __shfl_xor_sync(0xffffffffu, p, 4);
        p += __shfl_xor_sync(0xffffffffu, p, 8);
        if (n == 0) *yp = p;
        yp += DINNER;
    }
}

// -------------------- gate -> bf16 hi/lo planes -----------------------------
__global__ void gate_kernel(const float* __restrict__ ys,
                            const float* __restrict__ xin,
                            const float* __restrict__ xz,
                            const float* __restrict__ Dp,
                            __nv_bfloat16* __restrict__ yh,
                            __nv_bfloat16* __restrict__ yl) {
    int idx = blockIdx.x * blockDim.x + threadIdx.x;
    if (idx >= MTOT * DINNER) return;
    int e = idx % DINNER;
    int m = idx / DINNER;
    float z = xz[(size_t)m * TWOE + DINNER + e];
    float sil = z / (1.f + __expf(-z));
    float v = (ys[idx] + xin[idx] * Dp[e]) * sil;
    __nv_bfloat16 h, l;
    fsplit(v, h, l);
    yh[idx] = h; yl[idx] = l;
}

// ---------------------------------------------------------------------------
extern "C" void kernel_launch(void* const* d_in, const int* in_sizes, int n_in,
                              void* d_out, int out_size) {
    (void)in_sizes; (void)n_in; (void)out_size;
    const int*   tokens  = (const int*)  d_in[0];
    const float* embed   = (const float*)d_in[1];
    const float* norm_w  = (const float*)d_in[2];
    const float* in_w    = (const float*)d_in[3];
    const float* conv_w  = (const float*)d_in[4];
    const float* conv_b  = (const float*)d_in[5];
    const float* xp_w    = (const float*)d_in[6];
    const float* dt_w    = (const float*)d_in[7];
    const float* dt_b    = (const float*)d_in[8];
    const float* A_log   = (const float*)d_in[9];
    const float* D_param = (const float*)d_in[10];
    const float* out_w   = (const float*)d_in[11];
    const float* fnorm_w = (const float*)d_in[12];
    float* out = (float*)d_out;

    float *px, *pxz, *pxin, *pproj, *pdt, *pys;
    __nv_bfloat16 *pxnh, *pxnl, *pyh, *pyl, *pwih, *pwil, *pwoh, *pwol, *pweh, *pwel;
    cudaGetSymbolAddress((void**)&px,   g_x);
    cudaGetSymbolAddress((void**)&pxz,  g_xz);
    cudaGetSymbolAddress((void**)&pxin, g_xin);
    cudaGetSymbolAddress((void**)&pproj,g_proj);
    cudaGetSymbolAddress((void**)&pdt,  g_dt);
    cudaGetSymbolAddress((void**)&pys,  g_ys);
    cudaGetSymbolAddress((void**)&pxnh, g_xn_h);
    cudaGetSymbolAddress((void**)&pxnl, g_xn_l);
    cudaGetSymbolAddress((void**)&pyh,  g_y_h);
    cudaGetSymbolAddress((void**)&pyl,  g_y_l);
    cudaGetSymbolAddress((void**)&pwih, g_wi_h);
    cudaGetSymbolAddress((void**)&pwil, g_wi_l);
    cudaGetSymbolAddress((void**)&pwoh, g_wo_h);
    cudaGetSymbolAddress((void**)&pwol, g_wo_l);
    cudaGetSymbolAddress((void**)&pweh, g_we_h);
    cudaGetSymbolAddress((void**)&pwel, g_we_l);

    cudaFuncSetAttribute(mma_gemm_kernel<false,false>,
                         cudaFuncAttributeMaxDynamicSharedMemorySize, GSMEM);
    cudaFuncSetAttribute(mma_gemm_kernel<true,false>,
                         cudaFuncAttributeMaxDynamicSharedMemorySize, GSMEM);
    cudaFuncSetAttribute(mma_gemm_kernel<false,true>,
                         cudaFuncAttributeMaxDynamicSharedMemorySize, GSMEM);

    const int EW  = MTOT * DINNER;
    const int EWB = (EW + 255) / 256;
    const int GW  = (MTOT * DMODEL + 255) / 256;

    {
        int n1 = NLAYER * TWOE * DMODEL;
        split_kernel<<<(n1 + 255)/256, 256>>>(in_w, pwih, pwil, n1);
        int n2 = NLAYER * DMODEL * DINNER;
        split_kernel<<<(n2 + 255)/256, 256>>>(out_w, pwoh, pwol, n2);
        int n3 = VOCPAD * DMODEL;
        split_pad_kernel<<<(n3 + 255)/256, 256>>>(embed, pweh, pwel);
    }

    embed_gather_kernel<<<GW, 256>>>(tokens, embed, px);

    for (int i = 0; i < NLAYER; i++) {
        rmsnorm_kernel<<<MTOT/8, dim3(32,8)>>>(px, norm_w + i*DMODEL, pxnh, pxnl);

        mma_gemm_kernel<false,false><<<dim3(TWOE/128, MTOT/128), 256, GSMEM>>>(
            pxnh, pxnl, pwih + (size_t)i*TWOE*DMODEL, pwil + (size_t)i*TWOE*DMODEL,
            pxz, nullptr, TWOE, DMODEL);

        conv_silu_kernel<<<EWB, 256>>>(pxz, conv_w + i*DINNER*4, conv_b + i*DINNER, pxin);

        sgemm_kernel<64,64,16,4,4><<<dim3(1, MTOT/64), 256>>>(
            pxin, xp_w + (size_t)i*PROJC*DINNER, pproj, MTOT, PROJC, DINNER);

        dtproj_kernel<<<EWB, 256>>>(pproj, dt_w + (size_t)i*DINNER*DTRANK,
                                    dt_b + i*DINNER, pdt);

        scan_kernel<<<(BATCHN*DINNER/2)/8, 256>>>(pdt, pxin, pproj,
                                                  A_log + (size_t)i*DINNER*DSTATE, pys);

        gate_kernel<<<EWB, 256>>>(pys, pxin, pxz, D_param + i*DINNER, pyh, pyl);

        mma_gemm_kernel<true,false><<<dim3(DMODEL/128, MTOT/128), 256, GSMEM>>>(
            pyh, pyl, pwoh + (size_t)i*DMODEL*DINNER, pwol + (size_t)i*DMODEL*DINNER,
            px, px, DMODEL, DINNER);
    }

    rmsnorm_kernel<<<MTOT/8, dim3(32,8)>>>(px, fnorm_w, pxnh, pxnl);

    mma_gemm_kernel<false,true><<<dim3(VOCPAD/128, MTOT/128), 256, GSMEM>>>(
        pxnh, pxnl, pweh, pwel, out, nullptr, VOCABN, DMODEL);
}